// round 1
// baseline (speedup 1.0000x reference)
#include <cuda_runtime.h>
#include <stdint.h>

#define NB 8
#define NS 2048
#define ND 128
#define NH 4
#define NDK 32
#define NBS (NB*NS)

#define TQ 16
#define KT 256
#define SC_STRIDE 2056   // 2048 + 8 pad -> row banks offset by 8, conflict-free broadcasts

// ---- scratch (no allocations allowed) ----
__device__ float g_res[NBS*ND];
__device__ float g_Q[NBS*ND];
__device__ float g_K[NBS*ND];
__device__ float g_V[NBS*ND];
__device__ float g_ctx[NBS*ND];
__device__ int   g_mask4;

// ---- detect whether attn_mask is 1-byte (bool) or 4-byte (int32/float32) ----
// If elements are 4-byte with values 0/1 (int) or 0.0/1.0 (float), every byte at
// offset 1 (mod 4) is zero. With ~50% random ones, a 1-byte layout has a nonzero
// there with probability 1 - 2^-1024 over 1024 samples.
__global__ void detect_mask_kernel(const uint8_t* __restrict__ m) {
    int bad = 0;
    #pragma unroll 8
    for (int i = threadIdx.x; i < 1024; i += 32) bad |= (m[4*i + 1] != 0);
    unsigned any = __ballot_sync(0xffffffffu, bad);
    if (threadIdx.x == 0) g_mask4 = (any == 0) ? 1 : 0;
}

// ---- C[16384,128] = A[16384,128] @ W[128,128] ----
__global__ __launch_bounds__(256) void gemm128_kernel(
    const float* __restrict__ A, const float* __restrict__ W, float* __restrict__ C)
{
    extern __shared__ float sm[];
    float* ws = sm;            // 128*128
    float* as = sm + 128*128;  // 64*128
    int tid = threadIdx.x;
    int row0 = blockIdx.x * 64;

    const float4* W4 = (const float4*)W;
    float4* ws4 = (float4*)ws;
    for (int i = tid; i < 128*32; i += 256) ws4[i] = W4[i];
    const float4* A4 = (const float4*)(A + (size_t)row0 * ND);
    float4* as4 = (float4*)as;
    for (int i = tid; i < 64*32; i += 256) as4[i] = A4[i];
    __syncthreads();

    int tx = tid & 31, ty = tid >> 5;
    float acc[8][4];
    #pragma unroll
    for (int i = 0; i < 8; i++) { acc[i][0]=0.f; acc[i][1]=0.f; acc[i][2]=0.f; acc[i][3]=0.f; }

    #pragma unroll 4
    for (int d = 0; d < 128; d++) {
        float4 wv = ((const float4*)(ws + d*128))[tx];
        #pragma unroll
        for (int i = 0; i < 8; i++) {
            float a = as[(ty*8 + i)*128 + d];
            acc[i][0] += a*wv.x; acc[i][1] += a*wv.y;
            acc[i][2] += a*wv.z; acc[i][3] += a*wv.w;
        }
    }
    #pragma unroll
    for (int i = 0; i < 8; i++) {
        float4 v = make_float4(acc[i][0], acc[i][1], acc[i][2], acc[i][3]);
        *(float4*)(C + (size_t)(row0 + ty*8 + i)*ND + tx*4) = v;
    }
}

// ---- OUT = LayerNorm(CTX @ W + RES), fused ----
__global__ __launch_bounds__(256) void out_ln_kernel(
    const float* __restrict__ CTX, const float* __restrict__ RES,
    const float* __restrict__ W, float* __restrict__ OUT)
{
    extern __shared__ float sm[];
    float* ws = sm;
    float* as = sm + 128*128;
    int tid = threadIdx.x;
    int row0 = blockIdx.x * 64;

    const float4* W4 = (const float4*)W;
    float4* ws4 = (float4*)ws;
    for (int i = tid; i < 128*32; i += 256) ws4[i] = W4[i];
    const float4* A4 = (const float4*)(CTX + (size_t)row0 * ND);
    float4* as4 = (float4*)as;
    for (int i = tid; i < 64*32; i += 256) as4[i] = A4[i];
    __syncthreads();

    int tx = tid & 31, ty = tid >> 5;
    float acc[8][4];
    #pragma unroll
    for (int i = 0; i < 8; i++) { acc[i][0]=0.f; acc[i][1]=0.f; acc[i][2]=0.f; acc[i][3]=0.f; }

    #pragma unroll 4
    for (int d = 0; d < 128; d++) {
        float4 wv = ((const float4*)(ws + d*128))[tx];
        #pragma unroll
        for (int i = 0; i < 8; i++) {
            float a = as[(ty*8 + i)*128 + d];
            acc[i][0] += a*wv.x; acc[i][1] += a*wv.y;
            acc[i][2] += a*wv.z; acc[i][3] += a*wv.w;
        }
    }
    #pragma unroll
    for (int i = 0; i < 8; i++) {
        int row = row0 + ty*8 + i;
        float4 r4 = *(const float4*)(RES + (size_t)row*ND + tx*4);
        float x0 = acc[i][0] + r4.x;
        float x1 = acc[i][1] + r4.y;
        float x2 = acc[i][2] + r4.z;
        float x3 = acc[i][3] + r4.w;
        float s  = x0 + x1 + x2 + x3;
        float ss = x0*x0 + x1*x1 + x2*x2 + x3*x3;
        #pragma unroll
        for (int o = 16; o; o >>= 1) {
            s  += __shfl_xor_sync(0xffffffffu, s,  o);
            ss += __shfl_xor_sync(0xffffffffu, ss, o);
        }
        float mu  = s * (1.f/128.f);
        float var = ss * (1.f/128.f) - mu*mu;
        float rs  = rsqrtf(var + 1e-5f);
        float4 o4 = make_float4((x0-mu)*rs, (x1-mu)*rs, (x2-mu)*rs, (x3-mu)*rs);
        *(float4*)(OUT + (size_t)row*ND + tx*4) = o4;
    }
}

// ---- attention: scores + mask + softmax (full 16x2048 row tile in smem) + context ----
__global__ __launch_bounds__(256) void attn_kernel(
    const float* __restrict__ Qg, const float* __restrict__ Kg, const float* __restrict__ Vg,
    const uint8_t* __restrict__ mask, float* __restrict__ attn_out, float* __restrict__ ctx)
{
    extern __shared__ float sm[];
    float* sc = sm;                          // TQ * SC_STRIDE floats
    float* ks = sc + TQ*SC_STRIDE;           // KT * 36 floats (K tile, then V tile)
    float* qs = ks + KT*36;                  // TQ * 36 floats
    uint8_t* msk = (uint8_t*)(qs + TQ*36);   // TQ*KT bytes
    float* ctxp = (float*)msk;               // reused after scores: 2*TQ*NDK floats

    int tid = threadIdx.x;
    int q0 = blockIdx.x * TQ;
    int h  = blockIdx.y;
    int b  = blockIdx.z;
    const float scale = 0.17677669529663687f;  // 1/sqrt(32)

    // load Q tile
    for (int i = tid; i < TQ*NDK; i += 256) {
        int r = i >> 5, d = i & 31;
        qs[r*36 + d] = Qg[(size_t)(b*NS + q0 + r)*ND + h*NDK + d];
    }

    int sty = tid >> 6;   // 0..3 -> rows sty*4 + i
    int stx = tid & 63;   // cols stx + 64*j
    int m4 = g_mask4;

    // ---- scores: sc[r][k] for k = 0..2047, in 8 K-tiles of 256 ----
    for (int t = 0; t < 8; t++) {
        int k0 = t*KT;
        __syncthreads();   // qs ready (t==0), ks consumers done (t>0)
        for (int i = tid; i < KT*8; i += 256) {
            int kl = i >> 3, d4 = i & 7;
            float4 v = *(const float4*)(Kg + (size_t)(b*NS + k0 + kl)*ND + h*NDK + d4*4);
            *(float4*)(ks + kl*36 + d4*4) = v;
        }
        if (m4) {
            const unsigned* m32 = (const unsigned*)mask;
            for (int i = tid; i < TQ*KT; i += 256) {
                int r = i >> 8, kl = i & 255;
                msk[r*KT + kl] = (m32[(size_t)b*NS*NS + (size_t)(q0+r)*NS + k0 + kl] != 0u) ? 1 : 0;
            }
        } else {
            const unsigned* mw = (const unsigned*)mask;
            for (int i = tid; i < TQ*(KT/4); i += 256) {
                int r = i >> 6, w = i & 63;
                unsigned v = mw[((size_t)b*NS*NS + (size_t)(q0+r)*NS + k0) / 4 + w];
                msk[r*KT + w*4 + 0] = (v & 0x000000ffu) ? 1 : 0;
                msk[r*KT + w*4 + 1] = (v & 0x0000ff00u) ? 1 : 0;
                msk[r*KT + w*4 + 2] = (v & 0x00ff0000u) ? 1 : 0;
                msk[r*KT + w*4 + 3] = (v & 0xff000000u) ? 1 : 0;
            }
        }
        __syncthreads();

        float acc[4][4];
        #pragma unroll
        for (int i = 0; i < 4; i++)
            #pragma unroll
            for (int j = 0; j < 4; j++) acc[i][j] = 0.f;

        #pragma unroll
        for (int d4 = 0; d4 < 8; d4++) {
            float4 kv[4];
            #pragma unroll
            for (int j = 0; j < 4; j++)
                kv[j] = *(const float4*)(ks + (stx + 64*j)*36 + d4*4);
            #pragma unroll
            for (int i = 0; i < 4; i++) {
                float4 qv = *(const float4*)(qs + (sty*4 + i)*36 + d4*4);
                #pragma unroll
                for (int j = 0; j < 4; j++)
                    acc[i][j] += qv.x*kv[j].x + qv.y*kv[j].y + qv.z*kv[j].z + qv.w*kv[j].w;
            }
        }
        #pragma unroll
        for (int i = 0; i < 4; i++) {
            int r = sty*4 + i;
            #pragma unroll
            for (int j = 0; j < 4; j++) {
                int col = stx + 64*j;
                float sv = msk[r*KT + col] ? -1e9f : acc[i][j]*scale;
                sc[r*SC_STRIDE + k0 + col] = sv;
            }
        }
    }
    __syncthreads();

    // ---- softmax: 16 threads per row ----
    {
        int sr = tid >> 4, c16 = tid & 15;
        float* row = sc + sr*SC_STRIDE;
        float mx = -3.0e38f;
        for (int k = c16; k < NS; k += 16) mx = fmaxf(mx, row[k]);
        #pragma unroll
        for (int o = 8; o; o >>= 1) mx = fmaxf(mx, __shfl_xor_sync(0xffffffffu, mx, o));
        float ssum = 0.f;
        for (int k = c16; k < NS; k += 16) {
            float e = __expf(row[k] - mx);
            row[k] = e;
            ssum += e;
        }
        #pragma unroll
        for (int o = 8; o; o >>= 1) ssum += __shfl_xor_sync(0xffffffffu, ssum, o);
        float inv = 1.f / ssum;
        for (int k = c16; k < NS; k += 16) row[k] *= inv;
    }
    __syncthreads();

    // ---- optional attn output (contiguous rows: base + r*S + k == base + i) ----
    if (attn_out) {
        float* dst = attn_out + ((size_t)(b*NH + h)*NS + q0)*NS;
        for (int i = tid; i < TQ*NS; i += 256)
            dst[i] = sc[(i >> 11)*SC_STRIDE + (i & (NS-1))];
    }

    // ---- context: ctx[r][d] = sum_k sc[r][k] * V[k][d], k split across 2 halves ----
    int cc = tid & 7;          // d quad
    int cr = (tid >> 3) & 15;  // row
    int kh = tid >> 7;         // k half
    float4 cacc = make_float4(0.f, 0.f, 0.f, 0.f);
    for (int t = 0; t < 8; t++) {
        int k0 = t*KT;
        __syncthreads();
        for (int i = tid; i < KT*8; i += 256) {
            int kl = i >> 3, d4 = i & 7;
            float4 v = *(const float4*)(Vg + (size_t)(b*NS + k0 + kl)*ND + h*NDK + d4*4);
            *(float4*)(ks + kl*36 + d4*4) = v;
        }
        __syncthreads();
        int kbeg = kh*128, kend = kbeg + 128;
        #pragma unroll 4
        for (int kl = kbeg; kl < kend; kl++) {
            float a = sc[cr*SC_STRIDE + k0 + kl];
            float4 v = *(const float4*)(ks + kl*36 + cc*4);
            cacc.x += a*v.x; cacc.y += a*v.y; cacc.z += a*v.z; cacc.w += a*v.w;
        }
    }
    *(float4*)(ctxp + kh*(TQ*NDK) + cr*NDK + cc*4) = cacc;
    __syncthreads();
    if (tid < 128) {
        int r = tid >> 3, c = tid & 7;
        float4 a0 = *(const float4*)(ctxp + r*NDK + c*4);
        float4 a1 = *(const float4*)(ctxp + TQ*NDK + r*NDK + c*4);
        float4 s = make_float4(a0.x+a1.x, a0.y+a1.y, a0.z+a1.z, a0.w+a1.w);
        *(float4*)(ctx + (size_t)(b*NS + q0 + r)*ND + h*NDK + c*4) = s;
    }
}

extern "C" void kernel_launch(void* const* d_in, const int* in_sizes, int n_in,
                              void* d_out, int out_size) {
    const float*   inQ  = (const float*)d_in[0];
    const float*   inK  = (const float*)d_in[1];
    const float*   inV  = (const float*)d_in[2];
    const uint8_t* mask = (const uint8_t*)d_in[3];
    const float*   W0   = (const float*)d_in[4];
    const float*   Wq   = (const float*)d_in[5];
    const float*   Wk   = (const float*)d_in[6];
    const float*   Wv   = (const float*)d_in[7];
    const float*   Wo   = (const float*)d_in[8];

    float *res, *Qp, *Kp, *Vp, *ctxp;
    cudaGetSymbolAddress((void**)&res,  g_res);
    cudaGetSymbolAddress((void**)&Qp,   g_Q);
    cudaGetSymbolAddress((void**)&Kp,   g_K);
    cudaGetSymbolAddress((void**)&Vp,   g_V);
    cudaGetSymbolAddress((void**)&ctxp, g_ctx);

    const long long LN_N = (long long)NBS * ND;                 // 2,097,152
    const long long AT_N = (long long)NB * NH * NS * NS;        // 134,217,728
    float* ln_out   = (float*)d_out;
    float* attn_out = nullptr;
    long long osz = (long long)out_size;
    if (osz == LN_N) {
        attn_out = nullptr;
    } else if (osz == AT_N) {
        ln_out = nullptr;
        attn_out = (float*)d_out;
    } else {
        attn_out = (float*)d_out + LN_N;
    }

    const int SMEM_GEMM = (128*128 + 64*128) * 4;                       // 98304
    const int SMEM_ATTN = (TQ*SC_STRIDE + KT*36 + TQ*36) * 4 + TQ*KT;   // 174848

    cudaFuncSetAttribute(gemm128_kernel, cudaFuncAttributeMaxDynamicSharedMemorySize, SMEM_GEMM);
    cudaFuncSetAttribute(out_ln_kernel,  cudaFuncAttributeMaxDynamicSharedMemorySize, SMEM_GEMM);
    cudaFuncSetAttribute(attn_kernel,    cudaFuncAttributeMaxDynamicSharedMemorySize, SMEM_ATTN);

    detect_mask_kernel<<<1, 32>>>(mask);

    gemm128_kernel<<<NBS/64, 256, SMEM_GEMM>>>(inQ, W0, res);
    gemm128_kernel<<<NBS/64, 256, SMEM_GEMM>>>(inQ, Wq, Qp);
    gemm128_kernel<<<NBS/64, 256, SMEM_GEMM>>>(inK, Wk, Kp);
    gemm128_kernel<<<NBS/64, 256, SMEM_GEMM>>>(inV, Wv, Vp);

    dim3 ag(NS/TQ, NH, NB);
    attn_kernel<<<ag, 256, SMEM_ATTN>>>(Qp, Kp, Vp, mask, attn_out, ctxp);

    if (ln_out)
        out_ln_kernel<<<NBS/64, 256, SMEM_GEMM>>>(ctxp, res, Wo, ln_out);
}

// round 5
// speedup vs baseline: 2.9109x; 2.9109x over previous
#include <cuda_runtime.h>
#include <cuda_bf16.h>
#include <stdint.h>

#define NB 8
#define NS 2048
#define ND 128
#define NH 4
#define NDK 32
#define NBS (NB*NS)

// ---- scratch (no allocations allowed) ----
__device__ float g_res[NBS*ND];
__device__ float g_Q[NBS*ND];
__device__ float g_K[NBS*ND];
__device__ float g_V[NBS*ND];
__device__ float g_ctx[NBS*ND];
__device__ float g_L[NB*NH*NS];
__device__ unsigned g_maskbits[(size_t)NB*NS*NS/32];
__device__ int   g_mask4;

__device__ __forceinline__ uint32_t smem_u32(const void* p) {
    uint32_t a;
    asm("{ .reg .u64 t; cvta.to.shared.u64 t, %1; cvt.u32.u64 %0, t; }" : "=r"(a) : "l"(p));
    return a;
}
__device__ __forceinline__ uint32_t pack_bf16x2(float lo, float hi) {
    __nv_bfloat162 t = __floats2bfloat162_rn(lo, hi);
    return *reinterpret_cast<uint32_t*>(&t);
}

#define MMA16816(c0,c1,c2,c3,a0,a1,a2,a3,b0,b1) \
    asm volatile("mma.sync.aligned.m16n8k16.row.col.f32.bf16.bf16.f32 " \
        "{%0,%1,%2,%3}, {%4,%5,%6,%7}, {%8,%9}, {%0,%1,%2,%3};" \
        : "+f"(c0),"+f"(c1),"+f"(c2),"+f"(c3) \
        : "r"(a0),"r"(a1),"r"(a2),"r"(a3),"r"(b0),"r"(b1))

#define LDSM_X2(r0,r1,addr) \
    asm volatile("ldmatrix.sync.aligned.m8n8.x2.shared.b16 {%0,%1}, [%2];" \
        : "=r"(r0),"=r"(r1) : "r"(addr))
#define LDSM_X2T(r0,r1,addr) \
    asm volatile("ldmatrix.sync.aligned.m8n8.x2.trans.shared.b16 {%0,%1}, [%2];" \
        : "=r"(r0),"=r"(r1) : "r"(addr))
#define LDSM_X4(r0,r1,r2,r3,addr) \
    asm volatile("ldmatrix.sync.aligned.m8n8.x4.shared.b16 {%0,%1,%2,%3}, [%4];" \
        : "=r"(r0),"=r"(r1),"=r"(r2),"=r"(r3) : "r"(addr))

// smem byte offsets; row stride 80 B (32 bf16 data + 8 pad)
#define RSTR 80
#define SM_QH 0
#define SM_QL 10240
#define SM_KH 20480
#define SM_KL 30720
#define SM_V  40960
#define SMEM_ATTN 51200

// ---- detect whether attn_mask is 1-byte or 4-byte ----
__global__ void detect_mask_kernel(const uint8_t* __restrict__ m) {
    int bad = 0;
    #pragma unroll 8
    for (int i = threadIdx.x; i < 1024; i += 32) bad |= (m[4*i + 1] != 0);
    unsigned any = __ballot_sync(0xffffffffu, bad);
    if (threadIdx.x == 0) g_mask4 = (any == 0) ? 1 : 0;
}

// ---- pack mask into bits: bit=1 means masked ----
__global__ __launch_bounds__(256) void bitpack_mask_kernel(const uint8_t* __restrict__ m,
                                                           unsigned* __restrict__ bits) {
    size_t i = (size_t)blockIdx.x * 256 + threadIdx.x;
    bool v;
    if (g_mask4) v = ((const unsigned*)m)[i] != 0u;
    else         v = m[i] != 0;
    unsigned w = __ballot_sync(0xffffffffu, v);
    if ((threadIdx.x & 31) == 0) bits[i >> 5] = w;
}

// ---- C[16384,128] = A[16384,128] @ W[128,128] (fp32 SIMT) ----
__global__ __launch_bounds__(256) void gemm128_kernel(
    const float* __restrict__ A, const float* __restrict__ W, float* __restrict__ C)
{
    extern __shared__ float sm[];
    float* ws = sm;
    float* as = sm + 128*128;
    int tid = threadIdx.x;
    int row0 = blockIdx.x * 64;

    const float4* W4 = (const float4*)W;
    float4* ws4 = (float4*)ws;
    for (int i = tid; i < 128*32; i += 256) ws4[i] = W4[i];
    const float4* A4 = (const float4*)(A + (size_t)row0 * ND);
    float4* as4 = (float4*)as;
    for (int i = tid; i < 64*32; i += 256) as4[i] = A4[i];
    __syncthreads();

    int tx = tid & 31, ty = tid >> 5;
    float acc[8][4];
    #pragma unroll
    for (int i = 0; i < 8; i++) { acc[i][0]=0.f; acc[i][1]=0.f; acc[i][2]=0.f; acc[i][3]=0.f; }

    #pragma unroll 4
    for (int d = 0; d < 128; d++) {
        float4 wv = ((const float4*)(ws + d*128))[tx];
        #pragma unroll
        for (int i = 0; i < 8; i++) {
            float a = as[(ty*8 + i)*128 + d];
            acc[i][0] += a*wv.x; acc[i][1] += a*wv.y;
            acc[i][2] += a*wv.z; acc[i][3] += a*wv.w;
        }
    }
    #pragma unroll
    for (int i = 0; i < 8; i++) {
        float4 v = make_float4(acc[i][0], acc[i][1], acc[i][2], acc[i][3]);
        *(float4*)(C + (size_t)(row0 + ty*8 + i)*ND + tx*4) = v;
    }
}

// ---- OUT = LayerNorm(CTX @ W + RES) ----
__global__ __launch_bounds__(256) void out_ln_kernel(
    const float* __restrict__ CTX, const float* __restrict__ RES,
    const float* __restrict__ W, float* __restrict__ OUT)
{
    extern __shared__ float sm[];
    float* ws = sm;
    float* as = sm + 128*128;
    int tid = threadIdx.x;
    int row0 = blockIdx.x * 64;

    const float4* W4 = (const float4*)W;
    float4* ws4 = (float4*)ws;
    for (int i = tid; i < 128*32; i += 256) ws4[i] = W4[i];
    const float4* A4 = (const float4*)(CTX + (size_t)row0 * ND);
    float4* as4 = (float4*)as;
    for (int i = tid; i < 64*32; i += 256) as4[i] = A4[i];
    __syncthreads();

    int tx = tid & 31, ty = tid >> 5;
    float acc[8][4];
    #pragma unroll
    for (int i = 0; i < 8; i++) { acc[i][0]=0.f; acc[i][1]=0.f; acc[i][2]=0.f; acc[i][3]=0.f; }

    #pragma unroll 4
    for (int d = 0; d < 128; d++) {
        float4 wv = ((const float4*)(ws + d*128))[tx];
        #pragma unroll
        for (int i = 0; i < 8; i++) {
            float a = as[(ty*8 + i)*128 + d];
            acc[i][0] += a*wv.x; acc[i][1] += a*wv.y;
            acc[i][2] += a*wv.z; acc[i][3] += a*wv.w;
        }
    }
    #pragma unroll
    for (int i = 0; i < 8; i++) {
        int row = row0 + ty*8 + i;
        float4 r4 = *(const float4*)(RES + (size_t)row*ND + tx*4);
        float x0 = acc[i][0] + r4.x;
        float x1 = acc[i][1] + r4.y;
        float x2 = acc[i][2] + r4.z;
        float x3 = acc[i][3] + r4.w;
        float s  = x0 + x1 + x2 + x3;
        float ss = x0*x0 + x1*x1 + x2*x2 + x3*x3;
        #pragma unroll
        for (int o = 16; o; o >>= 1) {
            s  += __shfl_xor_sync(0xffffffffu, s,  o);
            ss += __shfl_xor_sync(0xffffffffu, ss, o);
        }
        float mu  = s * (1.f/128.f);
        float var = ss * (1.f/128.f) - mu*mu;
        float rs  = rsqrtf(var + 1e-5f);
        float4 o4 = make_float4((x0-mu)*rs, (x1-mu)*rs, (x2-mu)*rs, (x3-mu)*rs);
        *(float4*)(OUT + (size_t)row*ND + tx*4) = o4;
    }
}

// ======================= HMMA (mma.sync) attention =======================
// CTA: 256 thr (8 warps), 1 CTA = (b, h, 128 q rows). Warp w: q rows m0=16w..m0+15.
__global__ __launch_bounds__(256, 2) void attn_mma_kernel(
    const float* __restrict__ Qg, const float* __restrict__ Kg, const float* __restrict__ Vg,
    const unsigned* __restrict__ mbits, float* __restrict__ attn_out,
    float* __restrict__ ctx, float* __restrict__ Lrow)
{
    extern __shared__ char smc[];
    const uint32_t sb = smem_u32(smc);
    const int tid = threadIdx.x;
    const int wid = tid >> 5, lid = tid & 31;
    const int g = lid >> 2, tq = lid & 3;
    const int q0 = blockIdx.x * 128, h = blockIdx.y, b = blockIdx.z;
    const int m0 = wid * 16;
    const float scale = 0.17677669529663687f;  // 1/sqrt(32)

    const int lrow = tid >> 1, lhalf = tid & 1;   // cooperative tile loading split

    // ---- Q tile -> smem (hi/lo bf16) ----
    {
        const float* src = Qg + ((size_t)(b*NS) + q0 + lrow)*ND + h*NDK + lhalf*16;
        #pragma unroll
        for (int i = 0; i < 4; i++) {
            float4 v = *(const float4*)(src + i*4);
            float h0 = __bfloat162float(__float2bfloat16(v.x));
            float h1 = __bfloat162float(__float2bfloat16(v.y));
            float h2 = __bfloat162float(__float2bfloat16(v.z));
            float h3 = __bfloat162float(__float2bfloat16(v.w));
            int off = lrow*RSTR + lhalf*32 + i*8;
            *(uint32_t*)(smc + SM_QH + off)     = pack_bf16x2(h0, h1);
            *(uint32_t*)(smc + SM_QH + off + 4) = pack_bf16x2(h2, h3);
            *(uint32_t*)(smc + SM_QL + off)     = pack_bf16x2(v.x - h0, v.y - h1);
            *(uint32_t*)(smc + SM_QL + off + 4) = pack_bf16x2(v.z - h2, v.w - h3);
        }
    }
    __syncthreads();

    // ---- Q fragments (held for whole kernel): A[16 x 32] hi and lo ----
    uint32_t qh[2][4], ql[2][4];
    #pragma unroll
    for (int kc = 0; kc < 2; kc++) {
        uint32_t a = sb + SM_QH + (uint32_t)(m0 + (lid & 15))*RSTR + kc*32 + ((lid >> 4) & 1)*16;
        LDSM_X4(qh[kc][0], qh[kc][1], qh[kc][2], qh[kc][3], a);
        uint32_t a2 = a + (SM_QL - SM_QH);
        LDSM_X4(ql[kc][0], ql[kc][1], ql[kc][2], ql[kc][3], a2);
    }

    float cx[4][4];
    #pragma unroll
    for (int i = 0; i < 4; i++)
        #pragma unroll
        for (int j = 0; j < 4; j++) cx[i][j] = 0.f;
    float L0 = 0.f, L1 = 0.f;

    const size_t mr0 = ((size_t)b*NS + q0 + m0 + g) * (NS/32);
    const size_t mr1 = mr0 + (size_t)8 * (NS/32);

    for (int t = 0; t < 16; t++) {
        __syncthreads();   // previous tile fully consumed (and Q frags read on t=0)
        // ---- K tile (hi/lo) + V tile (bf16) -> smem ----
        {
            const float* ksrc = Kg + ((size_t)(b*NS) + t*128 + lrow)*ND + h*NDK + lhalf*16;
            const float* vsrc = Vg + ((size_t)(b*NS) + t*128 + lrow)*ND + h*NDK + lhalf*16;
            #pragma unroll
            for (int i = 0; i < 4; i++) {
                float4 v = *(const float4*)(ksrc + i*4);
                float h0 = __bfloat162float(__float2bfloat16(v.x));
                float h1 = __bfloat162float(__float2bfloat16(v.y));
                float h2 = __bfloat162float(__float2bfloat16(v.z));
                float h3 = __bfloat162float(__float2bfloat16(v.w));
                int off = lrow*RSTR + lhalf*32 + i*8;
                *(uint32_t*)(smc + SM_KH + off)     = pack_bf16x2(h0, h1);
                *(uint32_t*)(smc + SM_KH + off + 4) = pack_bf16x2(h2, h3);
                *(uint32_t*)(smc + SM_KL + off)     = pack_bf16x2(v.x - h0, v.y - h1);
                *(uint32_t*)(smc + SM_KL + off + 4) = pack_bf16x2(v.z - h2, v.w - h3);
                float4 w = *(const float4*)(vsrc + i*4);
                *(uint32_t*)(smc + SM_V + off)      = pack_bf16x2(w.x, w.y);
                *(uint32_t*)(smc + SM_V + off + 4)  = pack_bf16x2(w.z, w.w);
            }
        }
        // mask words for this thread's two rows (overlaps with STS latency)
        unsigned mw0[4], mw1[4];
        #pragma unroll
        for (int w = 0; w < 4; w++) {
            mw0[w] = mbits[mr0 + (size_t)t*4 + w];
            mw1[w] = mbits[mr1 + (size_t)t*4 + w];
        }
        __syncthreads();

        #pragma unroll
        for (int j = 0; j < 8; j++) {        // k-chunk of 16 score cols
            uint32_t aP[4];
            #pragma unroll
            for (int sub = 0; sub < 2; sub++) {
                int n0 = j*16 + sub*8;        // K rows for this 8-wide n-tile
                float c0 = 0.f, c1 = 0.f, c2 = 0.f, c3 = 0.f;
                #pragma unroll
                for (int kc = 0; kc < 2; kc++) {
                    uint32_t ka = sb + SM_KH + (uint32_t)(n0 + (lid & 7))*RSTR
                                + kc*32 + ((lid >> 3) & 1)*16;
                    uint32_t bh0, bh1, bl0, bl1;
                    LDSM_X2(bh0, bh1, ka);
                    LDSM_X2(bl0, bl1, ka + (SM_KL - SM_KH));
                    MMA16816(c0,c1,c2,c3, qh[kc][0],qh[kc][1],qh[kc][2],qh[kc][3], bh0,bh1);
                    MMA16816(c0,c1,c2,c3, qh[kc][0],qh[kc][1],qh[kc][2],qh[kc][3], bl0,bl1);
                    MMA16816(c0,c1,c2,c3, ql[kc][0],ql[kc][1],ql[kc][2],ql[kc][3], bh0,bh1);
                }
                int n = 2*j + sub;
                unsigned w0 = mw0[n >> 2], w1 = mw1[n >> 2];
                int bit = 8*(n & 3) + 2*tq;
                float p0 = ((w0 >> bit)     & 1u) ? 0.f : __expf(c0*scale);
                float p1 = ((w0 >> (bit+1)) & 1u) ? 0.f : __expf(c1*scale);
                float p2 = ((w1 >> bit)     & 1u) ? 0.f : __expf(c2*scale);
                float p3 = ((w1 >> (bit+1)) & 1u) ? 0.f : __expf(c3*scale);
                L0 += p0 + p1;
                L1 += p2 + p3;
                aP[sub*2 + 0] = pack_bf16x2(p0, p1);
                aP[sub*2 + 1] = pack_bf16x2(p2, p3);
                if (attn_out) {
                    float* dst = attn_out + (((size_t)(b*NH + h)*NS) + q0 + m0 + g)*NS
                               + t*128 + n*8 + 2*tq;
                    *(float2*)dst = make_float2(p0, p1);
                    *(float2*)(dst + (size_t)8*NS) = make_float2(p2, p3);
                }
            }
            // ---- PV: ctx += P(chunk j) @ V[16 rows, 32 d] ----
            #pragma unroll
            for (int dn = 0; dn < 4; dn++) {
                uint32_t va = sb + SM_V + (uint32_t)(j*16 + (lid & 15))*RSTR + dn*16;
                uint32_t vb0, vb1;
                LDSM_X2T(vb0, vb1, va);
                MMA16816(cx[dn][0], cx[dn][1], cx[dn][2], cx[dn][3],
                         aP[0], aP[1], aP[2], aP[3], vb0, vb1);
            }
        }
    }

    // ---- finish: reduce L across quad, normalize, write ctx ----
    L0 += __shfl_xor_sync(0xffffffffu, L0, 1);
    L0 += __shfl_xor_sync(0xffffffffu, L0, 2);
    L1 += __shfl_xor_sync(0xffffffffu, L1, 1);
    L1 += __shfl_xor_sync(0xffffffffu, L1, 2);
    float i0 = 1.f / L0, i1 = 1.f / L1;

    float* crow0 = ctx + ((size_t)(b*NS) + q0 + m0 + g)*ND + h*NDK;
    float* crow1 = crow0 + (size_t)8*ND;
    #pragma unroll
    for (int dn = 0; dn < 4; dn++) {
        *(float2*)(crow0 + dn*8 + 2*tq) = make_float2(cx[dn][0]*i0, cx[dn][1]*i0);
        *(float2*)(crow1 + dn*8 + 2*tq) = make_float2(cx[dn][2]*i1, cx[dn][3]*i1);
    }
    if (attn_out && tq == 0) {
        Lrow[((size_t)(b*NH + h))*NS + q0 + m0 + g]     = L0;
        Lrow[((size_t)(b*NH + h))*NS + q0 + m0 + g + 8] = L1;
    }
}

// ---- normalize attention probabilities (only when attn output requested) ----
__global__ __launch_bounds__(256) void rescale_attn_kernel(
    float* __restrict__ ao, const float* __restrict__ Lr)
{
    size_t row = blockIdx.x;
    float inv = 1.f / Lr[row];
    float4* p = (float4*)(ao + row * NS);
    for (int i = threadIdx.x; i < NS/4; i += 256) {
        float4 v = p[i];
        v.x *= inv; v.y *= inv; v.z *= inv; v.w *= inv;
        p[i] = v;
    }
}

extern "C" void kernel_launch(void* const* d_in, const int* in_sizes, int n_in,
                              void* d_out, int out_size) {
    const float*   inQ  = (const float*)d_in[0];
    const float*   inK  = (const float*)d_in[1];
    const float*   inV  = (const float*)d_in[2];
    const uint8_t* mask = (const uint8_t*)d_in[3];
    const float*   W0   = (const float*)d_in[4];
    const float*   Wq   = (const float*)d_in[5];
    const float*   Wk   = (const float*)d_in[6];
    const float*   Wv   = (const float*)d_in[7];
    const float*   Wo   = (const float*)d_in[8];

    float *res, *Qp, *Kp, *Vp, *ctxp, *Lp;
    unsigned* bits;
    cudaGetSymbolAddress((void**)&res,  g_res);
    cudaGetSymbolAddress((void**)&Qp,   g_Q);
    cudaGetSymbolAddress((void**)&Kp,   g_K);
    cudaGetSymbolAddress((void**)&Vp,   g_V);
    cudaGetSymbolAddress((void**)&ctxp, g_ctx);
    cudaGetSymbolAddress((void**)&Lp,   g_L);
    cudaGetSymbolAddress((void**)&bits, g_maskbits);

    const long long LN_N = (long long)NBS * ND;
    const long long AT_N = (long long)NB * NH * NS * NS;
    float* ln_out   = (float*)d_out;
    float* attn_out = nullptr;
    long long osz = (long long)out_size;
    if (osz == LN_N) {
        attn_out = nullptr;
    } else if (osz == AT_N) {
        ln_out = nullptr;
        attn_out = (float*)d_out;
    } else {
        attn_out = (float*)d_out + LN_N;
    }

    const int SMEM_GEMM = (128*128 + 64*128) * 4;
    cudaFuncSetAttribute(gemm128_kernel,  cudaFuncAttributeMaxDynamicSharedMemorySize, SMEM_GEMM);
    cudaFuncSetAttribute(out_ln_kernel,   cudaFuncAttributeMaxDynamicSharedMemorySize, SMEM_GEMM);
    cudaFuncSetAttribute(attn_mma_kernel, cudaFuncAttributeMaxDynamicSharedMemorySize, SMEM_ATTN);

    detect_mask_kernel<<<1, 32>>>(mask);
    bitpack_mask_kernel<<<(unsigned)((size_t)NB*NS*NS/256), 256>>>(mask, bits);

    gemm128_kernel<<<NBS/64, 256, SMEM_GEMM>>>(inQ, W0, res);
    gemm128_kernel<<<NBS/64, 256, SMEM_GEMM>>>(inQ, Wq, Qp);
    gemm128_kernel<<<NBS/64, 256, SMEM_GEMM>>>(inK, Wk, Kp);
    gemm128_kernel<<<NBS/64, 256, SMEM_GEMM>>>(inV, Wv, Vp);

    dim3 ag(NS/128, NH, NB);
    attn_mma_kernel<<<ag, 256, SMEM_ATTN>>>(Qp, Kp, Vp, bits, attn_out, ctxp, Lp);

    if (ln_out)
        out_ln_kernel<<<NBS/64, 256, SMEM_GEMM>>>(ctxp, res, Wo, ln_out);

    if (attn_out)
        rescale_attn_kernel<<<NB*NH*NS, 256>>>(attn_out, Lp);
}